// round 1
// baseline (speedup 1.0000x reference)
#include <cuda_runtime.h>
#include <math.h>

#define BSZ 8
#define SEQ 4096
#define DXX 1024
#define DHH 1024
#define M_TOTAL (BSZ * SEQ)   // 32768

// Scratch: k (later overwritten with h) and tilde_h. 128 MiB each.
__device__ float g_buf_k[(size_t)M_TOTAL * DHH];
__device__ float g_buf_th[(size_t)M_TOTAL * DHH];

// ---------------------------------------------------------------------------
// C[M,N] = A[M,K] * B[N,K]^T + bias[N]
// A row-major [M,K], Bw row-major [N,K] (weight layout: [out_dim, in_dim]).
// BM=BN=128, BK=8, 256 threads, 8x8 register microtile per thread.
// ---------------------------------------------------------------------------
__global__ __launch_bounds__(256) void gemm_bias_kernel(
    const float* __restrict__ A,
    const float* __restrict__ Bw,
    const float* __restrict__ bias,
    float* __restrict__ C,
    int M, int N, int K)
{
    __shared__ float As[8][128];
    __shared__ float Bs[8][128];

    const int tid = threadIdx.x;
    const int m0 = blockIdx.y * 128;
    const int n0 = blockIdx.x * 128;

    // loader mapping: each thread loads one float4 of A and one of B per K-tile
    const int lrow = tid >> 1;          // 0..127
    const int lkq  = (tid & 1) * 4;     // 0 or 4

    // compute mapping: 16x16 thread grid of 8x8 microtiles
    const int tm = (tid >> 4) * 8;      // 0..120
    const int tn = (tid & 15) * 8;      // 0..120

    float acc[8][8];
    #pragma unroll
    for (int i = 0; i < 8; ++i)
        #pragma unroll
        for (int j = 0; j < 8; ++j)
            acc[i][j] = 0.0f;

    const int ktiles = K >> 3;
    for (int kt = 0; kt < ktiles; ++kt) {
        const int k0 = kt << 3;

        // load A tile [128 x 8] -> As[k][m]
        {
            const float4 a4 = *(const float4*)(A + (size_t)(m0 + lrow) * K + k0 + lkq);
            As[lkq + 0][lrow] = a4.x;
            As[lkq + 1][lrow] = a4.y;
            As[lkq + 2][lrow] = a4.z;
            As[lkq + 3][lrow] = a4.w;
        }
        // load B tile [128 x 8] -> Bs[k][n]
        {
            const float4 b4 = *(const float4*)(Bw + (size_t)(n0 + lrow) * K + k0 + lkq);
            Bs[lkq + 0][lrow] = b4.x;
            Bs[lkq + 1][lrow] = b4.y;
            Bs[lkq + 2][lrow] = b4.z;
            Bs[lkq + 3][lrow] = b4.w;
        }
        __syncthreads();

        #pragma unroll
        for (int kk = 0; kk < 8; ++kk) {
            float4 a0 = *(const float4*)&As[kk][tm];
            float4 a1 = *(const float4*)&As[kk][tm + 4];
            float4 b0 = *(const float4*)&Bs[kk][tn];
            float4 b1 = *(const float4*)&Bs[kk][tn + 4];
            float ar[8] = {a0.x, a0.y, a0.z, a0.w, a1.x, a1.y, a1.z, a1.w};
            float br[8] = {b0.x, b0.y, b0.z, b0.w, b1.x, b1.y, b1.z, b1.w};
            #pragma unroll
            for (int i = 0; i < 8; ++i)
                #pragma unroll
                for (int j = 0; j < 8; ++j)
                    acc[i][j] = fmaf(ar[i], br[j], acc[i][j]);
        }
        __syncthreads();
    }

    // epilogue with bias
    #pragma unroll
    for (int i = 0; i < 8; ++i) {
        float* crow = C + (size_t)(m0 + tm + i) * N + n0 + tn;
        #pragma unroll
        for (int j = 0; j < 8; ++j)
            crow[j] = acc[i][j] + bias[n0 + tn + j];
    }
}

// ---------------------------------------------------------------------------
// Sequential scan: h_t = (1-z_t) h_{t-1} + z_t g(th_t)
//   z = sigmoid(k);  g(x) = x + 0.5 (x>=0), sigmoid(x) (x<0)
// One thread per (b, h) channel. Writes h in place over k buffer.
// ---------------------------------------------------------------------------
__global__ __launch_bounds__(256) void scan_kernel(
    float* __restrict__ kbuf,         // in: k, out: h
    const float* __restrict__ thbuf)  // in: tilde_h
{
    const int t = blockIdx.x * blockDim.x + threadIdx.x;   // 0..8191
    if (t >= BSZ * DHH) return;
    const int b = t >> 10;
    const int h = t & (DHH - 1);

    float* kp = kbuf + (size_t)b * SEQ * DHH + h;
    const float* tp = thbuf + (size_t)b * SEQ * DHH + h;

    float hprev = 0.0f;
    for (int s = 0; s < SEQ; ++s) {
        const size_t off = (size_t)s * DHH;
        float kv = kp[off];
        float th = tp[off];
        float z = 1.0f / (1.0f + __expf(-kv));
        float g = (th >= 0.0f) ? (th + 0.5f) : (1.0f / (1.0f + __expf(-th)));
        hprev = fmaf(z, g - hprev, hprev);
        kp[off] = hprev;
    }
}

extern "C" void kernel_launch(void* const* d_in, const int* in_sizes, int n_in,
                              void* d_out, int out_size)
{
    const float* x  = (const float*)d_in[0];  // [B,S,DX]
    const float* Wz = (const float*)d_in[1];  // [DH,DX]
    const float* bz = (const float*)d_in[2];  // [DH]
    const float* Wh = (const float*)d_in[3];  // [DH,DX]
    const float* bh = (const float*)d_in[4];  // [DH]
    const float* Wo = (const float*)d_in[5];  // [DX,DH]
    const float* bo = (const float*)d_in[6];  // [DX]
    float* out = (float*)d_out;               // [B,S,DX]

    float* kbuf = nullptr;
    float* thbuf = nullptr;
    cudaGetSymbolAddress((void**)&kbuf, g_buf_k);
    cudaGetSymbolAddress((void**)&thbuf, g_buf_th);

    dim3 grid(DHH / 128, M_TOTAL / 128);   // (8, 256)

    // k = x Wz^T + bz ; tilde_h = x Wh^T + bh
    gemm_bias_kernel<<<grid, 256>>>(x, Wz, bz, kbuf,  M_TOTAL, DHH, DXX);
    gemm_bias_kernel<<<grid, 256>>>(x, Wh, bh, thbuf, M_TOTAL, DHH, DXX);

    // recurrence over S (h written in place over kbuf)
    scan_kernel<<<(BSZ * DHH + 255) / 256, 256>>>(kbuf, thbuf);

    // out = h Wo^T + bo
    dim3 grid2(DXX / 128, M_TOTAL / 128);
    gemm_bias_kernel<<<grid2, 256>>>(kbuf, Wo, bo, out, M_TOTAL, DXX, DHH);
}

// round 3
// speedup vs baseline: 3.6572x; 3.6572x over previous
#include <cuda_runtime.h>
#include <cuda_bf16.h>
#include <stdint.h>

#define BSZ 8
#define SEQ 4096
#define M_TOTAL 32768
#define NCHUNK 32
#define CHLEN 128

// Scratch (allocation-free): fp32 work buffers + bf16 hi/lo split images
__device__ float g_buf_k[(size_t)M_TOTAL * 1024];        // k -> h
__device__ float g_buf_th[(size_t)M_TOTAL * 1024];       // tilde_h -> products
__device__ float g_carry[(size_t)NCHUNK * BSZ * 1024];
__device__ __nv_bfloat16 g_ah[(size_t)M_TOTAL * 1024];   // A hi (x, then h)
__device__ __nv_bfloat16 g_al[(size_t)M_TOTAL * 1024];   // A lo
__device__ __nv_bfloat16 g_wh[(size_t)3072 * 1024];      // [Wz;Wh;Wo] hi
__device__ __nv_bfloat16 g_wl[(size_t)3072 * 1024];      // lo

// ---------------------------------------------------------------------------
__device__ __forceinline__ uint32_t smem_u32(const void* p) {
    uint32_t a;
    asm("{ .reg .u64 t; cvta.to.shared.u64 t, %1; cvt.u32.u64 %0, t; }" : "=r"(a) : "l"(p));
    return a;
}
__device__ __forceinline__ void ldsm4(uint32_t* r, uint32_t addr) {
    asm volatile("ldmatrix.sync.aligned.m8n8.x4.shared.b16 {%0,%1,%2,%3}, [%4];"
                 : "=r"(r[0]), "=r"(r[1]), "=r"(r[2]), "=r"(r[3]) : "r"(addr));
}
__device__ __forceinline__ void mma16816(float* d, const uint32_t* a, uint32_t b0, uint32_t b1) {
    asm volatile(
        "mma.sync.aligned.m16n8k16.row.col.f32.bf16.bf16.f32 "
        "{%0,%1,%2,%3}, {%4,%5,%6,%7}, {%8,%9}, {%0,%1,%2,%3};"
        : "+f"(d[0]), "+f"(d[1]), "+f"(d[2]), "+f"(d[3])
        : "r"(a[0]), "r"(a[1]), "r"(a[2]), "r"(a[3]), "r"(b0), "r"(b1));
}
__device__ __forceinline__ void cp16(uint32_t saddr, const void* gaddr) {
    asm volatile("cp.async.cg.shared.global [%0], [%1], 16;" :: "r"(saddr), "l"(gaddr));
}

// SMEM: [0..512) bias, stages at 1024, 32KB each (Ah 8K | Al 8K | Bh 8K | Bl 8K)
#define STAGE_BYTES 32768
#define NSTAGE 4
#define SMEM_TOTAL (1024 + NSTAGE * STAGE_BYTES)

// ---------------------------------------------------------------------------
// fp32 -> bf16 hi/lo split, 4 elements per thread
// ---------------------------------------------------------------------------
__global__ void __launch_bounds__(256) split_kernel(
    const float4* __restrict__ src, uint2* __restrict__ dh, uint2* __restrict__ dl, int n4)
{
    int i = blockIdx.x * 256 + threadIdx.x;
    if (i >= n4) return;
    float4 v = src[i];
    __nv_bfloat16 h0 = __float2bfloat16_rn(v.x);
    __nv_bfloat16 h1 = __float2bfloat16_rn(v.y);
    __nv_bfloat16 h2 = __float2bfloat16_rn(v.z);
    __nv_bfloat16 h3 = __float2bfloat16_rn(v.w);
    __nv_bfloat16 l0 = __float2bfloat16_rn(v.x - __bfloat162float(h0));
    __nv_bfloat16 l1 = __float2bfloat16_rn(v.y - __bfloat162float(h1));
    __nv_bfloat16 l2 = __float2bfloat16_rn(v.z - __bfloat162float(h2));
    __nv_bfloat16 l3 = __float2bfloat16_rn(v.w - __bfloat162float(h3));
    uint2 hw, lw;
    hw.x = ((uint32_t)__bfloat16_as_ushort(h1) << 16) | __bfloat16_as_ushort(h0);
    hw.y = ((uint32_t)__bfloat16_as_ushort(h3) << 16) | __bfloat16_as_ushort(h2);
    lw.x = ((uint32_t)__bfloat16_as_ushort(l1) << 16) | __bfloat16_as_ushort(l0);
    lw.y = ((uint32_t)__bfloat16_as_ushort(l3) << 16) | __bfloat16_as_ushort(l2);
    dh[i] = hw;
    dl[i] = lw;
}

// ---------------------------------------------------------------------------
// HMMA GEMM, 3-term bf16 split: C = A * W^T + bias
// CTA 128x128, Kc=32, 4-stage cp.async pipeline, 8 warps of 64x32.
// ---------------------------------------------------------------------------
__device__ __forceinline__ void load_stage(
    uint32_t st,
    const __nv_bfloat16* __restrict__ Ah, const __nv_bfloat16* __restrict__ Al,
    const __nv_bfloat16* __restrict__ Bh, const __nv_bfloat16* __restrict__ Bl,
    int m0, int brow0, int k0, int tid)
{
    #pragma unroll
    for (int i = 0; i < 8; ++i) {
        const int id = i * 256 + tid;
        const int sec = i >> 1;
        const int cid = id & 511;
        const int r = cid >> 2;
        const int c = cid & 3;
        const __nv_bfloat16* gsrc;
        if (sec == 0)      gsrc = Ah + (size_t)(m0 + r) * 1024 + k0 + c * 8;
        else if (sec == 1) gsrc = Al + (size_t)(m0 + r) * 1024 + k0 + c * 8;
        else if (sec == 2) gsrc = Bh + (size_t)(brow0 + r) * 1024 + k0 + c * 8;
        else               gsrc = Bl + (size_t)(brow0 + r) * 1024 + k0 + c * 8;
        const uint32_t saddr = st + sec * 8192 + r * 64 + ((uint32_t)(c ^ ((r >> 1) & 3)) << 4);
        cp16(saddr, gsrc);
    }
}

__global__ void __launch_bounds__(256) gemm_hmma(
    const __nv_bfloat16* __restrict__ Ah, const __nv_bfloat16* __restrict__ Al,
    const __nv_bfloat16* __restrict__ Bh, const __nv_bfloat16* __restrict__ Bl,
    int wrow_off,
    const float* __restrict__ b0, const float* __restrict__ b1,
    float* __restrict__ C0, float* __restrict__ C1, int nsplit)
{
    extern __shared__ char smem[];
    const uint32_t sbase = smem_u32(smem);
    float* sbias = (float*)smem;

    const int tid = threadIdx.x;
    const int wid = tid >> 5;
    const int lane = tid & 31;
    const int m0 = blockIdx.y * 128;
    const int n0 = blockIdx.x * 128;
    const bool second = (n0 >= nsplit);
    const int nn = second ? (n0 - nsplit) : n0;
    const float* bias = second ? b1 : b0;
    float* C = second ? C1 : C0;
    const int brow0 = wrow_off + n0;

    if (tid < 128) sbias[tid] = bias[nn + tid];

    // prologue: stages 0..2
    #pragma unroll
    for (int s = 0; s < NSTAGE - 1; ++s) {
        load_stage(sbase + 1024 + s * STAGE_BYTES, Ah, Al, Bh, Bl, m0, brow0, s * 32, tid);
        asm volatile("cp.async.commit_group;" ::: "memory");
    }

    float acc[4][4][4];
    #pragma unroll
    for (int a = 0; a < 4; ++a)
        #pragma unroll
        for (int b = 0; b < 4; ++b)
            #pragma unroll
            for (int c = 0; c < 4; ++c)
                acc[a][b][c] = 0.0f;

    const int wm = (wid >> 2) * 64;
    const int wn = (wid & 3) * 32;
    const int sel = lane & 15;
    const int cext = lane >> 4;

    #pragma unroll 1
    for (int kt = 0; kt < 32; ++kt) {
        asm volatile("cp.async.wait_group 2;" ::: "memory");
        __syncthreads();

        const uint32_t st = sbase + 1024 + (kt & 3) * STAGE_BYTES;
        #pragma unroll
        for (int ks = 0; ks < 2; ++ks) {
            const int cch = ks * 2 + cext;
            uint32_t bhf[2][4], blf[2][4];
            #pragma unroll
            for (int ni2 = 0; ni2 < 2; ++ni2) {
                const int n = wn + ni2 * 16 + sel;
                const uint32_t off = (uint32_t)(n * 64) + ((uint32_t)(cch ^ ((n >> 1) & 3)) << 4);
                ldsm4(bhf[ni2], st + 16384 + off);
                ldsm4(blf[ni2], st + 24576 + off);
            }
            #pragma unroll
            for (int mi = 0; mi < 4; ++mi) {
                const int m = wm + mi * 16 + sel;
                const uint32_t off = (uint32_t)(m * 64) + ((uint32_t)(cch ^ ((m >> 1) & 3)) << 4);
                uint32_t ahf[4], alf[4];
                ldsm4(ahf, st + off);
                ldsm4(alf, st + 8192 + off);
                #pragma unroll
                for (int ni = 0; ni < 4; ++ni) {
                    const int ni2 = ni >> 1, jj = ni & 1;
                    mma16816(acc[mi][ni], ahf, bhf[ni2][jj], bhf[ni2][jj + 2]);
                    mma16816(acc[mi][ni], ahf, blf[ni2][jj], blf[ni2][jj + 2]);
                    mma16816(acc[mi][ni], alf, bhf[ni2][jj], bhf[ni2][jj + 2]);
                }
            }
        }

        if (kt + NSTAGE - 1 < 32) {
            load_stage(sbase + 1024 + ((kt + NSTAGE - 1) & 3) * STAGE_BYTES,
                       Ah, Al, Bh, Bl, m0, brow0, (kt + NSTAGE - 1) * 32, tid);
        }
        asm volatile("cp.async.commit_group;" ::: "memory");
    }

    // epilogue
    #pragma unroll
    for (int mi = 0; mi < 4; ++mi) {
        const int gm = m0 + wm + mi * 16 + (lane >> 2);
        #pragma unroll
        for (int ni = 0; ni < 4; ++ni) {
            const int col = wn + ni * 8 + (lane & 3) * 2;
            const float bv0 = sbias[col];
            const float bv1 = sbias[col + 1];
            float* p0 = C + (size_t)gm * 1024 + nn + col;
            float2 v;
            v.x = acc[mi][ni][0] + bv0;
            v.y = acc[mi][ni][1] + bv1;
            *(float2*)p0 = v;
            v.x = acc[mi][ni][2] + bv0;
            v.y = acc[mi][ni][3] + bv1;
            *(float2*)(p0 + 8 * 1024) = v;
        }
    }
}

// ---------------------------------------------------------------------------
// Chunked linear-recurrence scan
// ---------------------------------------------------------------------------
__global__ void __launch_bounds__(256) scan_stage1(float* __restrict__ kb,
                                                   float* __restrict__ th)
{
    const int t = blockIdx.x * 256 + threadIdx.x;       // 0 .. 262143
    const int chunk = t >> 13;
    const int cid = t & 8191;
    const size_t base = ((size_t)(cid >> 10) * SEQ + chunk * CHLEN) * 1024 + (cid & 1023);

    float h = 0.0f, p = 1.0f;
    #pragma unroll 4
    for (int s = 0; s < CHLEN; ++s) {
        const size_t off = base + (size_t)s * 1024;
        const float kv = kb[off];
        const float tv = th[off];
        const float z = 1.0f / (1.0f + __expf(-kv));
        const float a = 1.0f - z;
        const float g = (tv >= 0.0f) ? (tv + 0.5f) : (1.0f / (1.0f + __expf(-tv)));
        h = fmaf(a, h, z * g);
        p *= a;
        kb[off] = h;
        th[off] = p;
    }
}

__global__ void __launch_bounds__(256) scan_stage2(const float* __restrict__ kb,
                                                   const float* __restrict__ th,
                                                   float* __restrict__ carry)
{
    const int cid = blockIdx.x * 256 + threadIdx.x;
    if (cid >= BSZ * 1024) return;
    const int b = cid >> 10;
    const int hh = cid & 1023;
    float c = 0.0f;
    #pragma unroll 1
    for (int ck = 0; ck < NCHUNK; ++ck) {
        carry[(size_t)ck * 8192 + cid] = c;
        const size_t off = ((size_t)b * SEQ + ck * CHLEN + (CHLEN - 1)) * 1024 + hh;
        c = fmaf(th[off], c, kb[off]);
    }
}

__global__ void __launch_bounds__(256) scan_stage3(float* __restrict__ kb,
                                                   const float* __restrict__ th,
                                                   const float* __restrict__ carry)
{
    const size_t i4 = (size_t)blockIdx.x * 256 + threadIdx.x;
    const size_t e = i4 * 4;
    const size_t m = e >> 10;
    const int hh = (int)(e & 1023);
    const int b = (int)(m >> 12);
    const int s = (int)(m & 4095);
    const int ck = s >> 7;

    float4 h0 = *(float4*)(kb + e);
    const float4 p = *(const float4*)(th + e);
    const float4 cv = *(const float4*)(carry + (size_t)ck * 8192 + b * 1024 + hh);
    h0.x = fmaf(p.x, cv.x, h0.x);
    h0.y = fmaf(p.y, cv.y, h0.y);
    h0.z = fmaf(p.z, cv.z, h0.z);
    h0.w = fmaf(p.w, cv.w, h0.w);
    *(float4*)(kb + e) = h0;
}

// ---------------------------------------------------------------------------
extern "C" void kernel_launch(void* const* d_in, const int* in_sizes, int n_in,
                              void* d_out, int out_size)
{
    const float* x  = (const float*)d_in[0];
    const float* Wz = (const float*)d_in[1];
    const float* bz = (const float*)d_in[2];
    const float* Wh = (const float*)d_in[3];
    const float* bh = (const float*)d_in[4];
    const float* Wo = (const float*)d_in[5];
    const float* bo = (const float*)d_in[6];
    float* out = (float*)d_out;

    float *kbuf, *thbuf, *carry;
    __nv_bfloat16 *ah, *al, *wh, *wl;
    cudaGetSymbolAddress((void**)&kbuf,  g_buf_k);
    cudaGetSymbolAddress((void**)&thbuf, g_buf_th);
    cudaGetSymbolAddress((void**)&carry, g_carry);
    cudaGetSymbolAddress((void**)&ah, g_ah);
    cudaGetSymbolAddress((void**)&al, g_al);
    cudaGetSymbolAddress((void**)&wh, g_wh);
    cudaGetSymbolAddress((void**)&wl, g_wl);

    cudaFuncSetAttribute(gemm_hmma, cudaFuncAttributeMaxDynamicSharedMemorySize, SMEM_TOTAL);

    const int w4 = 1024 * 1024 / 4;       // elems/4 per W matrix
    split_kernel<<<w4 / 256, 256>>>((const float4*)Wz, (uint2*)wh, (uint2*)wl, w4);
    split_kernel<<<w4 / 256, 256>>>((const float4*)Wh,
                                    (uint2*)(wh + (size_t)1024 * 1024),
                                    (uint2*)(wl + (size_t)1024 * 1024), w4);
    split_kernel<<<w4 / 256, 256>>>((const float4*)Wo,
                                    (uint2*)(wh + (size_t)2048 * 1024),
                                    (uint2*)(wl + (size_t)2048 * 1024), w4);

    const int x4 = (int)((size_t)M_TOTAL * 1024 / 4);
    split_kernel<<<x4 / 256, 256>>>((const float4*)x, (uint2*)ah, (uint2*)al, x4);

    // fused input GEMMs: k | tilde_h
    {
        dim3 grid(16, 256);
        gemm_hmma<<<grid, 256, SMEM_TOTAL>>>(ah, al, wh, wl, 0, bz, bh, kbuf, thbuf, 1024);
    }

    scan_stage1<<<(BSZ * 1024 * NCHUNK) / 256, 256>>>(kbuf, thbuf);
    scan_stage2<<<(BSZ * 1024) / 256, 256>>>(kbuf, thbuf, carry);
    scan_stage3<<<(int)(((size_t)M_TOTAL * 1024 / 4) / 256), 256>>>(kbuf, thbuf, carry);

    // split h, then output GEMM
    split_kernel<<<x4 / 256, 256>>>((const float4*)kbuf, (uint2*)ah, (uint2*)al, x4);
    {
        dim3 grid(8, 256);
        gemm_hmma<<<grid, 256, SMEM_TOTAL>>>(ah, al, wh, wl, 2048, bo, bo, out, out, 1 << 30);
    }
}

// round 4
// speedup vs baseline: 5.8561x; 1.6012x over previous
#include <cuda_runtime.h>
#include <cuda_fp16.h>
#include <stdint.h>

#define BSZ 8
#define SEQ 4096
#define M_TOTAL 32768
#define NCHUNK 32
#define CHLEN 128

// Scratch (allocation-free)
__device__ float g_buf_k[(size_t)M_TOTAL * 1024];        // k -> h0 (chunk-local)
__device__ float g_buf_th[(size_t)M_TOTAL * 1024];       // tilde_h -> products
__device__ float g_carry[(size_t)NCHUNK * BSZ * 1024];
__device__ __half g_ah[(size_t)M_TOTAL * 1024];          // A hi (x, then h)
__device__ __half g_al[(size_t)M_TOTAL * 1024];          // A lo
__device__ __half g_wf[(size_t)3072 * 1024];             // [Wz;Wh;Wo] fp16

// ---------------------------------------------------------------------------
__device__ __forceinline__ uint32_t smem_u32(const void* p) {
    uint32_t a;
    asm("{ .reg .u64 t; cvta.to.shared.u64 t, %1; cvt.u32.u64 %0, t; }" : "=r"(a) : "l"(p));
    return a;
}
__device__ __forceinline__ void ldsm4(uint32_t* r, uint32_t addr) {
    asm volatile("ldmatrix.sync.aligned.m8n8.x4.shared.b16 {%0,%1,%2,%3}, [%4];"
                 : "=r"(r[0]), "=r"(r[1]), "=r"(r[2]), "=r"(r[3]) : "r"(addr));
}
__device__ __forceinline__ void mma16816(float* d, const uint32_t* a, uint32_t b0, uint32_t b1) {
    asm volatile(
        "mma.sync.aligned.m16n8k16.row.col.f32.f16.f16.f32 "
        "{%0,%1,%2,%3}, {%4,%5,%6,%7}, {%8,%9}, {%0,%1,%2,%3};"
        : "+f"(d[0]), "+f"(d[1]), "+f"(d[2]), "+f"(d[3])
        : "r"(a[0]), "r"(a[1]), "r"(a[2]), "r"(a[3]), "r"(b0), "r"(b1));
}
__device__ __forceinline__ void cp16(uint32_t saddr, const void* gaddr) {
    asm volatile("cp.async.cg.shared.global [%0], [%1], 16;" :: "r"(saddr), "l"(gaddr));
}
__device__ __forceinline__ uint2 pack_h4(__half a, __half b, __half c, __half d) {
    uint2 r;
    r.x = ((uint32_t)__half_as_ushort(b) << 16) | __half_as_ushort(a);
    r.y = ((uint32_t)__half_as_ushort(d) << 16) | __half_as_ushort(c);
    return r;
}

// SMEM: [0..512) bias; stages at 1024, 24KB each (Ah 8K | Al 8K | W 8K)
#define STAGE_BYTES 24576
#define NSTAGE 4
#define SMEM_TOTAL (1024 + NSTAGE * STAGE_BYTES)   // 99328

// ---------------------------------------------------------------------------
// splits
// ---------------------------------------------------------------------------
__global__ void __launch_bounds__(256) split_w_kernel(
    const float4* __restrict__ Wz, const float4* __restrict__ Wh,
    const float4* __restrict__ Wo, uint2* __restrict__ dst)
{
    const int i = blockIdx.x * 256 + threadIdx.x;   // 0 .. 786431
    const int mat = i >> 18;
    const int off = i & 262143;
    const float4* src = (mat == 0) ? Wz : (mat == 1) ? Wh : Wo;
    const float4 v = src[off];
    dst[i] = pack_h4(__float2half_rn(v.x), __float2half_rn(v.y),
                     __float2half_rn(v.z), __float2half_rn(v.w));
}

__global__ void __launch_bounds__(256) split_a_kernel(
    const float4* __restrict__ src, uint2* __restrict__ dh, uint2* __restrict__ dl,
    int base)
{
    const int i = base + blockIdx.x * 256 + threadIdx.x;
    const float4 v = src[i];
    const __half h0 = __float2half_rn(v.x);
    const __half h1 = __float2half_rn(v.y);
    const __half h2 = __float2half_rn(v.z);
    const __half h3 = __float2half_rn(v.w);
    dh[i] = pack_h4(h0, h1, h2, h3);
    dl[i] = pack_h4(__float2half_rn(v.x - __half2float(h0)),
                    __float2half_rn(v.y - __half2float(h1)),
                    __float2half_rn(v.z - __half2float(h2)),
                    __float2half_rn(v.w - __half2float(h3)));
}

// ---------------------------------------------------------------------------
// HMMA GEMM, 2-term fp16 split: C = (Ah+Al) * W^T + bias
// CTA 128x128, Kc=32, 4-stage cp.async, 8 warps of 64x32, 2 CTA/SM.
// ---------------------------------------------------------------------------
__device__ __forceinline__ void load_stage(
    uint32_t st,
    const __half* __restrict__ Ah, const __half* __restrict__ Al,
    const __half* __restrict__ Wf,
    int m0, int brow0, int k0, int tid)
{
    #pragma unroll
    for (int i = 0; i < 6; ++i) {
        const int id = i * 256 + tid;
        const int sec = id >> 9;
        const int cid = id & 511;
        const int r = cid >> 2;
        const int c = cid & 3;
        const __half* gsrc;
        if (sec == 0)      gsrc = Ah + (size_t)(m0 + r) * 1024 + k0 + c * 8;
        else if (sec == 1) gsrc = Al + (size_t)(m0 + r) * 1024 + k0 + c * 8;
        else               gsrc = Wf + (size_t)(brow0 + r) * 1024 + k0 + c * 8;
        const uint32_t saddr = st + sec * 8192 + r * 64 + ((uint32_t)(c ^ ((r >> 1) & 3)) << 4);
        cp16(saddr, gsrc);
    }
}

__global__ void __launch_bounds__(256, 2) gemm_hmma(
    const __half* __restrict__ Ah, const __half* __restrict__ Al,
    const __half* __restrict__ Wf, int wrow_off,
    const float* __restrict__ b0, const float* __restrict__ b1,
    float* __restrict__ C0, float* __restrict__ C1, int nsplit)
{
    extern __shared__ char smem[];
    const uint32_t sbase = smem_u32(smem);
    float* sbias = (float*)smem;

    const int tid = threadIdx.x;
    const int wid = tid >> 5;
    const int lane = tid & 31;
    const int m0 = blockIdx.y * 128;
    const int n0 = blockIdx.x * 128;
    const bool second = (n0 >= nsplit);
    const int nn = second ? (n0 - nsplit) : n0;
    const float* bias = second ? b1 : b0;
    float* C = second ? C1 : C0;
    const int brow0 = wrow_off + n0;

    if (tid < 128) sbias[tid] = bias[nn + tid];

    #pragma unroll
    for (int s = 0; s < NSTAGE - 1; ++s) {
        load_stage(sbase + 1024 + s * STAGE_BYTES, Ah, Al, Wf, m0, brow0, s * 32, tid);
        asm volatile("cp.async.commit_group;" ::: "memory");
    }

    float acc[4][4][4];
    #pragma unroll
    for (int a = 0; a < 4; ++a)
        #pragma unroll
        for (int b = 0; b < 4; ++b)
            #pragma unroll
            for (int c = 0; c < 4; ++c)
                acc[a][b][c] = 0.0f;

    const int wm = (wid >> 2) * 64;
    const int wn = (wid & 3) * 32;
    const int sel = lane & 15;
    const int cext = lane >> 4;

    #pragma unroll 1
    for (int kt = 0; kt < 32; ++kt) {
        asm volatile("cp.async.wait_group 2;" ::: "memory");
        __syncthreads();

        const uint32_t st = sbase + 1024 + (kt & 3) * STAGE_BYTES;
        #pragma unroll
        for (int ks = 0; ks < 2; ++ks) {
            const int cch = ks * 2 + cext;
            uint32_t wfr[2][4];
            #pragma unroll
            for (int ni2 = 0; ni2 < 2; ++ni2) {
                const int n = wn + ni2 * 16 + sel;
                const uint32_t off = (uint32_t)(n * 64) + ((uint32_t)(cch ^ ((n >> 1) & 3)) << 4);
                ldsm4(wfr[ni2], st + 16384 + off);
            }
            #pragma unroll
            for (int mi = 0; mi < 4; ++mi) {
                const int m = wm + mi * 16 + sel;
                const uint32_t off = (uint32_t)(m * 64) + ((uint32_t)(cch ^ ((m >> 1) & 3)) << 4);
                uint32_t ahf[4], alf[4];
                ldsm4(ahf, st + off);
                ldsm4(alf, st + 8192 + off);
                #pragma unroll
                for (int ni = 0; ni < 4; ++ni) {
                    const int ni2 = ni >> 1, jj = ni & 1;
                    mma16816(acc[mi][ni], ahf, wfr[ni2][jj], wfr[ni2][jj + 2]);
                    mma16816(acc[mi][ni], alf, wfr[ni2][jj], wfr[ni2][jj + 2]);
                }
            }
        }

        if (kt + NSTAGE - 1 < 32) {
            load_stage(sbase + 1024 + ((kt + NSTAGE - 1) & 3) * STAGE_BYTES,
                       Ah, Al, Wf, m0, brow0, (kt + NSTAGE - 1) * 32, tid);
        }
        asm volatile("cp.async.commit_group;" ::: "memory");
    }

    #pragma unroll
    for (int mi = 0; mi < 4; ++mi) {
        const int gm = m0 + wm + mi * 16 + (lane >> 2);
        #pragma unroll
        for (int ni = 0; ni < 4; ++ni) {
            const int col = wn + ni * 8 + (lane & 3) * 2;
            const float bv0 = sbias[col];
            const float bv1 = sbias[col + 1];
            float* p0 = C + (size_t)gm * 1024 + nn + col;
            float2 v;
            v.x = acc[mi][ni][0] + bv0;
            v.y = acc[mi][ni][1] + bv1;
            *(float2*)p0 = v;
            v.x = acc[mi][ni][2] + bv0;
            v.y = acc[mi][ni][3] + bv1;
            *(float2*)(p0 + 8 * 1024) = v;
        }
    }
}

// ---------------------------------------------------------------------------
// Chunked linear-recurrence scan
// ---------------------------------------------------------------------------
__global__ void __launch_bounds__(256) scan_stage1(float* __restrict__ kb,
                                                   float* __restrict__ th)
{
    const int t = blockIdx.x * 256 + threadIdx.x;
    const int chunk = t >> 13;
    const int cid = t & 8191;
    const size_t base = ((size_t)(cid >> 10) * SEQ + chunk * CHLEN) * 1024 + (cid & 1023);

    float h = 0.0f, p = 1.0f;
    #pragma unroll 4
    for (int s = 0; s < CHLEN; ++s) {
        const size_t off = base + (size_t)s * 1024;
        const float kv = kb[off];
        const float tv = th[off];
        const float z = 1.0f / (1.0f + __expf(-kv));
        const float a = 1.0f - z;
        const float g = (tv >= 0.0f) ? (tv + 0.5f) : (1.0f / (1.0f + __expf(-tv)));
        h = fmaf(a, h, z * g);
        p *= a;
        kb[off] = h;
        th[off] = p;
    }
}

__global__ void __launch_bounds__(256) scan_stage2(const float* __restrict__ kb,
                                                   const float* __restrict__ th,
                                                   float* __restrict__ carry)
{
    const int cid = blockIdx.x * 256 + threadIdx.x;
    if (cid >= BSZ * 1024) return;
    const int b = cid >> 10;
    const int hh = cid & 1023;
    float c = 0.0f;
    #pragma unroll 1
    for (int ck = 0; ck < NCHUNK; ++ck) {
        carry[(size_t)ck * 8192 + cid] = c;
        const size_t off = ((size_t)b * SEQ + ck * CHLEN + (CHLEN - 1)) * 1024 + hh;
        c = fmaf(th[off], c, kb[off]);
    }
}

// stage3: finalize h and emit fp16 hi/lo split directly (no fp32 h write)
__global__ void __launch_bounds__(256) scan_stage3(const float* __restrict__ kb,
                                                   const float* __restrict__ th,
                                                   const float* __restrict__ carry,
                                                   uint2* __restrict__ dh,
                                                   uint2* __restrict__ dl)
{
    const size_t i4 = (size_t)blockIdx.x * 256 + threadIdx.x;
    const size_t e = i4 * 4;
    const size_t m = e >> 10;
    const int hh = (int)(e & 1023);
    const int b = (int)(m >> 12);
    const int s = (int)(m & 4095);
    const int ck = s >> 7;

    float4 h0 = *(const float4*)(kb + e);
    const float4 p = *(const float4*)(th + e);
    const float4 cv = *(const float4*)(carry + (size_t)ck * 8192 + b * 1024 + hh);
    h0.x = fmaf(p.x, cv.x, h0.x);
    h0.y = fmaf(p.y, cv.y, h0.y);
    h0.z = fmaf(p.z, cv.z, h0.z);
    h0.w = fmaf(p.w, cv.w, h0.w);

    const __half a0 = __float2half_rn(h0.x);
    const __half a1 = __float2half_rn(h0.y);
    const __half a2 = __float2half_rn(h0.z);
    const __half a3 = __float2half_rn(h0.w);
    dh[i4] = pack_h4(a0, a1, a2, a3);
    dl[i4] = pack_h4(__float2half_rn(h0.x - __half2float(a0)),
                     __float2half_rn(h0.y - __half2float(a1)),
                     __float2half_rn(h0.z - __half2float(a2)),
                     __float2half_rn(h0.w - __half2float(a3)));
}

// ---------------------------------------------------------------------------
extern "C" void kernel_launch(void* const* d_in, const int* in_sizes, int n_in,
                              void* d_out, int out_size)
{
    const float* x  = (const float*)d_in[0];
    const float* Wz = (const float*)d_in[1];
    const float* bz = (const float*)d_in[2];
    const float* Wh = (const float*)d_in[3];
    const float* bh = (const float*)d_in[4];
    const float* Wo = (const float*)d_in[5];
    const float* bo = (const float*)d_in[6];
    float* out = (float*)d_out;

    float *kbuf, *thbuf, *carry;
    __half *ah, *al, *wf;
    cudaGetSymbolAddress((void**)&kbuf,  g_buf_k);
    cudaGetSymbolAddress((void**)&thbuf, g_buf_th);
    cudaGetSymbolAddress((void**)&carry, g_carry);
    cudaGetSymbolAddress((void**)&ah, g_ah);
    cudaGetSymbolAddress((void**)&al, g_al);
    cudaGetSymbolAddress((void**)&wf, g_wf);

    static bool attr_done = false;
    if (!attr_done) {
        cudaFuncSetAttribute(gemm_hmma,
                             cudaFuncAttributeMaxDynamicSharedMemorySize, SMEM_TOTAL);
        attr_done = true;
    }

    // 1: fused W split (fp16)
    split_w_kernel<<<3072, 256>>>((const float4*)Wz, (const float4*)Wh,
                                  (const float4*)Wo, (uint2*)wf);

    // 2,3: x split (fp16 hi/lo), two halves
    const int x4 = (int)((size_t)M_TOTAL * 1024 / 4);   // 8388608
    split_a_kernel<<<x4 / 512, 256>>>((const float4*)x, (uint2*)ah, (uint2*)al, 0);
    split_a_kernel<<<x4 / 512, 256>>>((const float4*)x, (uint2*)ah, (uint2*)al, x4 / 2);

    // 4: fused input GEMMs: k | tilde_h  (N = 2048 logical)
    {
        dim3 grid(16, 256);
        gemm_hmma<<<grid, 256, SMEM_TOTAL>>>(ah, al, wf, 0, bz, bh, kbuf, thbuf, 1024);
    }

    // 5-7: chunked scan (stage3 emits fp16 split of h)
    scan_stage1<<<(BSZ * 1024 * NCHUNK) / 256, 256>>>(kbuf, thbuf);
    scan_stage2<<<(BSZ * 1024) / 256, 256>>>(kbuf, thbuf, carry);
    scan_stage3<<<x4 / 256, 256>>>(kbuf, thbuf, carry, (uint2*)ah, (uint2*)al);

    // 8: out = h Wo^T + bo
    {
        dim3 grid(8, 256);
        gemm_hmma<<<grid, 256, SMEM_TOTAL>>>(ah, al, wf, 2048, bo, bo, out, out, 1 << 30);
    }
}

// round 6
// speedup vs baseline: 9.4121x; 1.6072x over previous
#include <cuda_runtime.h>
#include <cuda_fp16.h>
#include <stdint.h>

#define BSZ 8
#define SEQ 4096
#define M_TOTAL 32768
#define NCHUNK 32
#define CHLEN 128

// Scratch (allocation-free)
__device__ float g_buf_k[(size_t)M_TOTAL * 1024];        // k -> h0 (chunk-local)
__device__ float g_buf_th[(size_t)M_TOTAL * 1024];       // tilde_h -> products
__device__ float g_carry[(size_t)NCHUNK * BSZ * 1024];
__device__ __half g_ah[(size_t)M_TOTAL * 1024];          // A fp16 (x, then h)
__device__ __half g_wf[(size_t)3072 * 1024];             // [Wz;Wh;Wo] fp16

// ---------------------------------------------------------------------------
__device__ __forceinline__ uint32_t smem_u32(const void* p) {
    uint32_t a;
    asm("{ .reg .u64 t; cvta.to.shared.u64 t, %1; cvt.u32.u64 %0, t; }" : "=r"(a) : "l"(p));
    return a;
}
__device__ __forceinline__ void ldsm4(uint32_t* r, uint32_t addr) {
    asm volatile("ldmatrix.sync.aligned.m8n8.x4.shared.b16 {%0,%1,%2,%3}, [%4];"
                 : "=r"(r[0]), "=r"(r[1]), "=r"(r[2]), "=r"(r[3]) : "r"(addr));
}
__device__ __forceinline__ void mma16816(float* d, const uint32_t* a, uint32_t b0, uint32_t b1) {
    asm volatile(
        "mma.sync.aligned.m16n8k16.row.col.f32.f16.f16.f32 "
        "{%0,%1,%2,%3}, {%4,%5,%6,%7}, {%8,%9}, {%0,%1,%2,%3};"
        : "+f"(d[0]), "+f"(d[1]), "+f"(d[2]), "+f"(d[3])
        : "r"(a[0]), "r"(a[1]), "r"(a[2]), "r"(a[3]), "r"(b0), "r"(b1));
}
__device__ __forceinline__ void cp16(uint32_t saddr, const void* gaddr) {
    asm volatile("cp.async.cg.shared.global [%0], [%1], 16;" :: "r"(saddr), "l"(gaddr));
}
__device__ __forceinline__ uint2 pack_h4(__half a, __half b, __half c, __half d) {
    uint2 r;
    r.x = ((uint32_t)__half_as_ushort(b) << 16) | __half_as_ushort(a);
    r.y = ((uint32_t)__half_as_ushort(d) << 16) | __half_as_ushort(c);
    return r;
}

// SMEM: [0..512) bias; stages at 1024, 16KB each (A 8K | W 8K)
#define STAGE_BYTES 16384
#define NSTAGE 4
#define SMEM_TOTAL (1024 + NSTAGE * STAGE_BYTES)   // 66560

// ---------------------------------------------------------------------------
// conversions
// ---------------------------------------------------------------------------
__global__ void __launch_bounds__(256) split_w_kernel(
    const float4* __restrict__ Wz, const float4* __restrict__ Wh,
    const float4* __restrict__ Wo, uint2* __restrict__ dst)
{
    const int i = blockIdx.x * 256 + threadIdx.x;   // 0 .. 786431
    const int mat = i >> 18;
    const int off = i & 262143;
    const float4* src = (mat == 0) ? Wz : (mat == 1) ? Wh : Wo;
    const float4 v = src[off];
    dst[i] = pack_h4(__float2half_rn(v.x), __float2half_rn(v.y),
                     __float2half_rn(v.z), __float2half_rn(v.w));
}

__global__ void __launch_bounds__(256) split_a_kernel(
    const float4* __restrict__ src, uint2* __restrict__ dh, int base)
{
    const int i = base + blockIdx.x * 256 + threadIdx.x;
    const float4 v = src[i];
    dh[i] = pack_h4(__float2half_rn(v.x), __float2half_rn(v.y),
                    __float2half_rn(v.z), __float2half_rn(v.w));
}

// ---------------------------------------------------------------------------
// HMMA GEMM fp16xfp16->fp32: C = A * W^T + bias
// CTA 128x128, Kc=32, 4-stage cp.async, 8 warps of 64x32, 2 CTA/SM.
// ---------------------------------------------------------------------------
__device__ __forceinline__ void load_stage(
    uint32_t st,
    const __half* __restrict__ Ah, const __half* __restrict__ Wf,
    int m0, int brow0, int k0, int tid)
{
    #pragma unroll
    for (int i = 0; i < 4; ++i) {
        const int id = i * 256 + tid;
        const int sec = id >> 9;             // 0 = A, 1 = W
        const int cid = id & 511;
        const int r = cid >> 2;
        const int c = cid & 3;
        const __half* gsrc = (sec == 0)
            ? Ah + (size_t)(m0 + r) * 1024 + k0 + c * 8
            : Wf + (size_t)(brow0 + r) * 1024 + k0 + c * 8;
        const uint32_t saddr = st + sec * 8192 + r * 64 + ((uint32_t)(c ^ ((r >> 1) & 3)) << 4);
        cp16(saddr, gsrc);
    }
}

__global__ void __launch_bounds__(256, 2) gemm_hmma(
    const __half* __restrict__ Ah, const __half* __restrict__ Wf, int wrow_off,
    const float* __restrict__ b0, const float* __restrict__ b1,
    float* __restrict__ C0, float* __restrict__ C1, int nsplit)
{
    extern __shared__ char smem[];
    const uint32_t sbase = smem_u32(smem);
    float* sbias = (float*)smem;

    const int tid = threadIdx.x;
    const int wid = tid >> 5;
    const int lane = tid & 31;
    const int m0 = blockIdx.y * 128;
    const int n0 = blockIdx.x * 128;
    const bool second = (n0 >= nsplit);
    const int nn = second ? (n0 - nsplit) : n0;
    const float* bias = second ? b1 : b0;
    float* C = second ? C1 : C0;
    const int brow0 = wrow_off + n0;

    if (tid < 128) sbias[tid] = bias[nn + tid];

    #pragma unroll
    for (int s = 0; s < NSTAGE - 1; ++s) {
        load_stage(sbase + 1024 + s * STAGE_BYTES, Ah, Wf, m0, brow0, s * 32, tid);
        asm volatile("cp.async.commit_group;" ::: "memory");
    }

    float acc[4][4][4];
    #pragma unroll
    for (int a = 0; a < 4; ++a)
        #pragma unroll
        for (int b = 0; b < 4; ++b)
            #pragma unroll
            for (int c = 0; c < 4; ++c)
                acc[a][b][c] = 0.0f;

    const int wm = (wid >> 2) * 64;
    const int wn = (wid & 3) * 32;
    const int sel = lane & 15;
    const int cext = lane >> 4;

    #pragma unroll 1
    for (int kt = 0; kt < 32; ++kt) {
        asm volatile("cp.async.wait_group 2;" ::: "memory");
        __syncthreads();

        const uint32_t st = sbase + 1024 + (kt & 3) * STAGE_BYTES;
        #pragma unroll
        for (int ks = 0; ks < 2; ++ks) {
            const int cch = ks * 2 + cext;
            uint32_t wfr[2][4];
            #pragma unroll
            for (int ni2 = 0; ni2 < 2; ++ni2) {
                const int n = wn + ni2 * 16 + sel;
                const uint32_t off = (uint32_t)(n * 64) + ((uint32_t)(cch ^ ((n >> 1) & 3)) << 4);
                ldsm4(wfr[ni2], st + 8192 + off);
            }
            #pragma unroll
            for (int mi = 0; mi < 4; ++mi) {
                const int m = wm + mi * 16 + sel;
                const uint32_t off = (uint32_t)(m * 64) + ((uint32_t)(cch ^ ((m >> 1) & 3)) << 4);
                uint32_t ahf[4];
                ldsm4(ahf, st + off);
                #pragma unroll
                for (int ni = 0; ni < 4; ++ni) {
                    const int ni2 = ni >> 1, jj = ni & 1;
                    mma16816(acc[mi][ni], ahf, wfr[ni2][jj], wfr[ni2][jj + 2]);
                }
            }
        }

        if (kt + NSTAGE - 1 < 32) {
            load_stage(sbase + 1024 + ((kt + NSTAGE - 1) & 3) * STAGE_BYTES,
                       Ah, Wf, m0, brow0, (kt + NSTAGE - 1) * 32, tid);
        }
        asm volatile("cp.async.commit_group;" ::: "memory");
    }

    #pragma unroll
    for (int mi = 0; mi < 4; ++mi) {
        const int gm = m0 + wm + mi * 16 + (lane >> 2);
        #pragma unroll
        for (int ni = 0; ni < 4; ++ni) {
            const int col = wn + ni * 8 + (lane & 3) * 2;
            const float bv0 = sbias[col];
            const float bv1 = sbias[col + 1];
            float* p0 = C + (size_t)gm * 1024 + nn + col;
            float2 v;
            v.x = acc[mi][ni][0] + bv0;
            v.y = acc[mi][ni][1] + bv1;
            *(float2*)p0 = v;
            v.x = acc[mi][ni][2] + bv0;
            v.y = acc[mi][ni][3] + bv1;
            *(float2*)(p0 + 8 * 1024) = v;
        }
    }
}

// ---------------------------------------------------------------------------
// Chunked linear-recurrence scan
// ---------------------------------------------------------------------------
__global__ void __launch_bounds__(256) scan_stage1(float* __restrict__ kb,
                                                   float* __restrict__ th)
{
    const int t = blockIdx.x * 256 + threadIdx.x;
    const int chunk = t >> 13;
    const int cid = t & 8191;
    const size_t base = ((size_t)(cid >> 10) * SEQ + chunk * CHLEN) * 1024 + (cid & 1023);

    float h = 0.0f, p = 1.0f;
    #pragma unroll 4
    for (int s = 0; s < CHLEN; ++s) {
        const size_t off = base + (size_t)s * 1024;
        const float kv = kb[off];
        const float tv = th[off];
        const float z = 1.0f / (1.0f + __expf(-kv));
        const float a = 1.0f - z;
        const float g = (tv >= 0.0f) ? (tv + 0.5f) : (1.0f / (1.0f + __expf(-tv)));
        h = fmaf(a, h, z * g);
        p *= a;
        kb[off] = h;
        th[off] = p;
    }
}

__global__ void __launch_bounds__(256) scan_stage2(const float* __restrict__ kb,
                                                   const float* __restrict__ th,
                                                   float* __restrict__ carry)
{
    const int cid = blockIdx.x * 256 + threadIdx.x;
    if (cid >= BSZ * 1024) return;
    const int b = cid >> 10;
    const int hh = cid & 1023;
    float c = 0.0f;
    #pragma unroll 1
    for (int ck = 0; ck < NCHUNK; ++ck) {
        carry[(size_t)ck * 8192 + cid] = c;
        const size_t off = ((size_t)b * SEQ + ck * CHLEN + (CHLEN - 1)) * 1024 + hh;
        c = fmaf(th[off], c, kb[off]);
    }
}

// stage3: finalize h and emit fp16 directly
__global__ void __launch_bounds__(256) scan_stage3(const float* __restrict__ kb,
                                                   const float* __restrict__ th,
                                                   const float* __restrict__ carry,
                                                   uint2* __restrict__ dh)
{
    const size_t i4 = (size_t)blockIdx.x * 256 + threadIdx.x;
    const size_t e = i4 * 4;
    const size_t m = e >> 10;
    const int hh = (int)(e & 1023);
    const int b = (int)(m >> 12);
    const int s = (int)(m & 4095);
    const int ck = s >> 7;

    float4 h0 = *(const float4*)(kb + e);
    const float4 p = *(const float4*)(th + e);
    const float4 cv = *(const float4*)(carry + (size_t)ck * 8192 + b * 1024 + hh);
    h0.x = fmaf(p.x, cv.x, h0.x);
    h0.y = fmaf(p.y, cv.y, h0.y);
    h0.z = fmaf(p.z, cv.z, h0.z);
    h0.w = fmaf(p.w, cv.w, h0.w);

    dh[i4] = pack_h4(__float2half_rn(h0.x), __float2half_rn(h0.y),
                     __float2half_rn(h0.z), __float2half_rn(h0.w));
}

// ---------------------------------------------------------------------------
extern "C" void kernel_launch(void* const* d_in, const int* in_sizes, int n_in,
                              void* d_out, int out_size)
{
    const float* x  = (const float*)d_in[0];
    const float* Wz = (const float*)d_in[1];
    const float* bz = (const float*)d_in[2];
    const float* Wh = (const float*)d_in[3];
    const float* bh = (const float*)d_in[4];
    const float* Wo = (const float*)d_in[5];
    const float* bo = (const float*)d_in[6];
    float* out = (float*)d_out;

    float *kbuf, *thbuf, *carry;
    __half *ah, *wf;
    cudaGetSymbolAddress((void**)&kbuf,  g_buf_k);
    cudaGetSymbolAddress((void**)&thbuf, g_buf_th);
    cudaGetSymbolAddress((void**)&carry, g_carry);
    cudaGetSymbolAddress((void**)&ah, g_ah);
    cudaGetSymbolAddress((void**)&wf, g_wf);

    static bool attr_done = false;
    if (!attr_done) {
        cudaFuncSetAttribute(gemm_hmma,
                             cudaFuncAttributeMaxDynamicSharedMemorySize, SMEM_TOTAL);
        attr_done = true;
    }

    // 1: fused W conversion (fp16)
    split_w_kernel<<<3072, 256>>>((const float4*)Wz, (const float4*)Wh,
                                  (const float4*)Wo, (uint2*)wf);

    // 2: x conversion (fp16)
    const int x4 = (int)((size_t)M_TOTAL * 1024 / 4);   // 8388608
    split_a_kernel<<<x4 / 256, 256>>>((const float4*)x, (uint2*)ah, 0);

    // 3: fused input GEMMs: k | tilde_h  (N = 2048 logical)
    {
        dim3 grid(16, 256);
        gemm_hmma<<<grid, 256, SMEM_TOTAL>>>(ah, wf, 0, bz, bh, kbuf, thbuf, 1024);
    }

    // 4-6: chunked scan (stage3 emits fp16 h)
    scan_stage1<<<(BSZ * 1024 * NCHUNK) / 256, 256>>>(kbuf, thbuf);
    scan_stage2<<<(BSZ * 1024) / 256, 256>>>(kbuf, thbuf, carry);
    scan_stage3<<<x4 / 256, 256>>>(kbuf, thbuf, carry, (uint2*)ah);

    // 7: out = h Wo^T + bo
    {
        dim3 grid(8, 256);
        gemm_hmma<<<grid, 256, SMEM_TOTAL>>>(ah, wf, 2048, bo, bo, out, out, 1 << 30);
    }
}